// round 6
// baseline (speedup 1.0000x reference)
#include <cuda_runtime.h>

// ComplexityAnalyzer: per-image 64-bin histogram + L1 normalize + 64->32->128 MLP.
// Inputs (metadata order): grad_map [B*512*512] f32, W1 [32*64], b1 [32],
//                          W2 [128*32], b2 [128]. Output: [B*128] f32.
//
// R6: atomic-free histogram. Per-thread byte-packed counters in smem,
// TRANSPOSED (cnt[word][tid]) so each lane always hits its own bank ->
// conflict-free LDS/STS at full crossbar rate, replacing the shared-atomic
// pipe (~4.8 lane-ops/cyc) that bound all previous rounds. Two flush periods
// (128 elems each) keep byte counters overflow-safe; flush uses dp4a
// byte-lane extraction with staggered, conflict-free reads.

#define THREADS 1024
#define ITERS   64            // 512*512/4 float4 per image / 1024 threads
#define HALF    32            // flush every 32 iters (128 elems/thread <= 255)
#define CNT_WORDS (16 * THREADS)   // 16 packed words x 1024 threads = 64 KB

__global__ __launch_bounds__(THREADS, 1)
void ca_hist_mlp_kernel(const float* __restrict__ grad,
                        const float* __restrict__ W1, const float* __restrict__ b1,
                        const float* __restrict__ W2, const float* __restrict__ b2,
                        float* __restrict__ out)
{
    extern __shared__ unsigned int cnt[];          // [16][1024] transposed, 64 KB
    __shared__ unsigned int fhi[64];
    __shared__ float fh[64];
    __shared__ float hmid[32];
    __shared__ float inv_s;

    const int tid = threadIdx.x;
    const int img = blockIdx.x;

    // Zero counters + accumulators
    #pragma unroll
    for (int w = 0; w < 16; ++w)
        cnt[w * THREADS + tid] = 0u;
    if (tid < 64) fhi[tid] = 0u;
    __syncthreads();

    const float4* src = (const float4*)(grad + (size_t)img * 262144u) + tid;
    unsigned int* mycnt = cnt + tid;

    const float scale = 64.0f / 255.0f;
    const float magic = 8388608.0f;  // 2^23

    #pragma unroll 1
    for (int half = 0; half < 2; ++half) {
        // ---- counting period: 32 iters x 4 elems/thread ----
        #pragma unroll 4
        for (int it = 0; it < HALF; ++it) {
            float4 v = __ldg(&src[(half * HALF + it) * THREADS]);
            float q0, q1, q2, q3;
            // fma.rz: exact product + 2^23 truncated -> low mantissa = floor(v*64/255)
            asm("fma.rz.f32 %0, %1, %2, %3;" : "=f"(q0) : "f"(v.x), "f"(scale), "f"(magic));
            asm("fma.rz.f32 %0, %1, %2, %3;" : "=f"(q1) : "f"(v.y), "f"(scale), "f"(magic));
            asm("fma.rz.f32 %0, %1, %2, %3;" : "=f"(q2) : "f"(v.z), "f"(scale), "f"(magic));
            asm("fma.rz.f32 %0, %1, %2, %3;" : "=f"(q3) : "f"(v.w), "f"(scale), "f"(magic));
            unsigned b0 = __float_as_uint(q0) & 0x3Fu;
            unsigned b1_ = __float_as_uint(q1) & 0x3Fu;
            unsigned b2_ = __float_as_uint(q2) & 0x3Fu;
            unsigned b3_ = __float_as_uint(q3) & 0x3Fu;
            // Sequential per-thread updates: RAW-safe for same-word collisions.
            mycnt[(b0 >> 2) << 10] += 1u << ((b0 & 3u) << 3);
            mycnt[(b1_ >> 2) << 10] += 1u << ((b1_ & 3u) << 3);
            mycnt[(b2_ >> 2) << 10] += 1u << ((b2_ & 3u) << 3);
            mycnt[(b3_ >> 2) << 10] += 1u << ((b3_ & 3u) << 3);
        }
        __syncthreads();

        // ---- flush: bin = tid>>4, k = tid&15 sums 64 words each ----
        {
            const int bin = tid >> 4;
            const int k   = tid & 15;
            const unsigned mask = 1u << ((bin & 3) << 3);   // dp4a byte-lane select
            const unsigned int* base = cnt + ((bin >> 2) << 10) + (k << 6);
            int acc = 0;
            #pragma unroll 8
            for (int i = 0; i < 64; ++i) {
                unsigned w = base[(i + 2 * k) & 63];        // staggered: conflict-free
                acc = __dp4a((int)w, (int)mask, acc);
            }
            #pragma unroll
            for (int off = 8; off > 0; off >>= 1)
                acc += __shfl_down_sync(0xFFFFFFFFu, acc, off, 16);
            if (k == 0) fhi[bin] += (unsigned)acc;          // single writer per bin
        }
        __syncthreads();

        if (half == 0) {
            // rezero counters for the second period
            #pragma unroll
            for (int w = 0; w < 16; ++w)
                cnt[w * THREADS + tid] = 0u;
            __syncthreads();
        }
    }

    if (tid < 64) fh[tid] = (float)fhi[tid];
    __syncthreads();

    // L1 norm denominator
    if (tid < 32) {
        float s = fh[tid] + fh[tid + 32];
        #pragma unroll
        for (int off = 16; off > 0; off >>= 1)
            s += __shfl_down_sync(0xFFFFFFFFu, s, off);
        if (tid == 0) inv_s = 1.0f / fmaxf(s, 1e-12f);
    }
    __syncthreads();
    if (tid < 64) fh[tid] *= inv_s;
    __syncthreads();

    // Layer 1: 64 -> 32 with ReLU
    if (tid < 32) {
        float acc = b1[tid];
        const float* w = W1 + tid * 64;
        #pragma unroll
        for (int b = 0; b < 64; ++b) acc = fmaf(fh[b], w[b], acc);
        hmid[tid] = fmaxf(acc, 0.0f);
    }
    __syncthreads();

    // Layer 2: 32 -> 128
    if (tid < 128) {
        float acc = b2[tid];
        const float* w = W2 + tid * 32;
        #pragma unroll
        for (int j = 0; j < 32; ++j) acc = fmaf(hmid[j], w[j], acc);
        out[img * 128 + tid] = acc;
    }
}

extern "C" void kernel_launch(void* const* d_in, const int* in_sizes, int n_in,
                              void* d_out, int out_size) {
    const float* grad = (const float*)d_in[0];
    const float* W1   = (const float*)d_in[1];
    const float* b1   = (const float*)d_in[2];
    const float* W2   = (const float*)d_in[3];
    const float* b2   = (const float*)d_in[4];
    float* out = (float*)d_out;

    static int smem_set = 0;   // idempotent attribute (not a work guard)
    if (!smem_set) {
        cudaFuncSetAttribute(ca_hist_mlp_kernel,
                             cudaFuncAttributeMaxDynamicSharedMemorySize,
                             CNT_WORDS * 4);
        smem_set = 1;
    }

    int B = in_sizes[0] / (512 * 512);
    ca_hist_mlp_kernel<<<B, THREADS, CNT_WORDS * 4>>>(grad, W1, b1, W2, b2, out);
}

// round 7
// speedup vs baseline: 1.1079x; 1.1079x over previous
#include <cuda_runtime.h>

// ComplexityAnalyzer: per-image 64-bin histogram + L1 normalize + 64->32->128 MLP.
// Inputs: grad_map [B*512*512] f32, W1 [32*64], b1 [32], W2 [128*32], b2 [128].
// Output: [B*128] f32.
//
// R7: atomic-free histogram via TWO disjoint transposed byte-counter arrays
// (A: words 0-15, B: words 16-31; cnt[word][tid] so every lane owns its bank,
// conflict-free). Elems x,y -> A; z,w -> B: chains provably independent, so
// no serialization (R6's failure). 128 elems/thread/array max -> byte counters
// never overflow -> single end-of-kernel dp4a flush. Depth-2 LDG prefetch.

#define THREADS 1024
#define ITERS   64                 // 512*512/4 float4 / 1024 threads
#define CNT_WORDS (32 * THREADS)   // 2 arrays x 16 words x 1024 thr = 128 KB

__global__ __launch_bounds__(THREADS, 1)
void ca_hist_mlp_kernel(const float* __restrict__ grad,
                        const float* __restrict__ W1, const float* __restrict__ b1,
                        const float* __restrict__ W2, const float* __restrict__ b2,
                        float* __restrict__ out)
{
    extern __shared__ unsigned int cnt[];     // [32][1024] transposed
    __shared__ float fh[64];
    __shared__ float hmid[32];
    __shared__ float inv_s;

    const int tid = threadIdx.x;
    const int img = blockIdx.x;

    #pragma unroll
    for (int w = 0; w < 32; ++w)
        cnt[w * THREADS + tid] = 0u;
    __syncthreads();

    const float4* src = (const float4*)(grad + (size_t)img * 262144u) + tid;
    unsigned int* cntA = cnt + tid;                    // words 0..15
    unsigned int* cntB = cnt + (16 << 10) + tid;       // words 16..31 (disjoint)

    const float scale = 64.0f / 255.0f;
    const float magic = 8388608.0f;  // 2^23

    // bin = low mantissa bits of fma.rz(v, 64/255, 2^23); always in [0,63]
    #define PROC(v)                                                                  \
        do {                                                                         \
            float q0, q1, q2, q3;                                                    \
            asm("fma.rz.f32 %0, %1, %2, %3;" : "=f"(q0) : "f"((v).x), "f"(scale), "f"(magic)); \
            asm("fma.rz.f32 %0, %1, %2, %3;" : "=f"(q1) : "f"((v).y), "f"(scale), "f"(magic)); \
            asm("fma.rz.f32 %0, %1, %2, %3;" : "=f"(q2) : "f"((v).z), "f"(scale), "f"(magic)); \
            asm("fma.rz.f32 %0, %1, %2, %3;" : "=f"(q3) : "f"((v).w), "f"(scale), "f"(magic)); \
            unsigned m0 = __float_as_uint(q0), m1 = __float_as_uint(q1);             \
            unsigned m2 = __float_as_uint(q2), m3 = __float_as_uint(q3);             \
            cntA[(m0 & 0x3Cu) << 8] += 1u << ((m0 & 3u) << 3);                       \
            cntA[(m1 & 0x3Cu) << 8] += 1u << ((m1 & 3u) << 3);                       \
            cntB[(m2 & 0x3Cu) << 8] += 1u << ((m2 & 3u) << 3);                       \
            cntB[(m3 & 0x3Cu) << 8] += 1u << ((m3 & 3u) << 3);                       \
        } while (0)

    // Depth-2 register prefetch, unroll 2
    float4 v0 = __ldg(&src[0]);
    float4 v1 = __ldg(&src[THREADS]);
    #pragma unroll 2
    for (int it = 0; it < ITERS - 2; it += 2) {
        float4 n0 = __ldg(&src[(it + 2) * THREADS]);
        float4 n1 = __ldg(&src[(it + 3) * THREADS]);
        PROC(v0);
        PROC(v1);
        v0 = n0;
        v1 = n1;
    }
    PROC(v0);
    PROC(v1);
    __syncthreads();

    // Flush: bin = tid>>4, 16 lanes/bin each sum 64 thread-columns of A and B.
    {
        const int bin = tid >> 4;
        const int k   = tid & 15;
        const unsigned mask = 1u << ((bin & 3) << 3);    // dp4a byte-lane select
        const unsigned wOff = (unsigned)(bin >> 2) << 10;
        const unsigned int* baseA = cnt + wOff + (k << 6);
        const unsigned int* baseB = baseA + (16 << 10);
        int acc = 0;
        #pragma unroll 8
        for (int i = 0; i < 64; ++i) {
            int idx = (i + 2 * k) & 63;                  // staggered: conflict-free
            acc = __dp4a((int)baseA[idx], (int)mask, acc);
            acc = __dp4a((int)baseB[idx], (int)mask, acc);
        }
        #pragma unroll
        for (int off = 8; off > 0; off >>= 1)
            acc += __shfl_down_sync(0xFFFFFFFFu, acc, off, 16);
        if (k == 0) fh[bin] = (float)acc;
    }
    __syncthreads();

    // L1 norm denominator
    if (tid < 32) {
        float s = fh[tid] + fh[tid + 32];
        #pragma unroll
        for (int off = 16; off > 0; off >>= 1)
            s += __shfl_down_sync(0xFFFFFFFFu, s, off);
        if (tid == 0) inv_s = 1.0f / fmaxf(s, 1e-12f);
    }
    __syncthreads();
    if (tid < 64) fh[tid] *= inv_s;
    __syncthreads();

    // Layer 1: 64 -> 32 with ReLU
    if (tid < 32) {
        float acc = b1[tid];
        const float* w = W1 + tid * 64;
        #pragma unroll
        for (int b = 0; b < 64; ++b) acc = fmaf(fh[b], w[b], acc);
        hmid[tid] = fmaxf(acc, 0.0f);
    }
    __syncthreads();

    // Layer 2: 32 -> 128
    if (tid < 128) {
        float acc = b2[tid];
        const float* w = W2 + tid * 32;
        #pragma unroll
        for (int j = 0; j < 32; ++j) acc = fmaf(hmid[j], w[j], acc);
        out[img * 128 + tid] = acc;
    }
}

extern "C" void kernel_launch(void* const* d_in, const int* in_sizes, int n_in,
                              void* d_out, int out_size) {
    const float* grad = (const float*)d_in[0];
    const float* W1   = (const float*)d_in[1];
    const float* b1   = (const float*)d_in[2];
    const float* W2   = (const float*)d_in[3];
    const float* b2   = (const float*)d_in[4];
    float* out = (float*)d_out;

    static int smem_set = 0;   // idempotent attribute (not a work guard)
    if (!smem_set) {
        cudaFuncSetAttribute(ca_hist_mlp_kernel,
                             cudaFuncAttributeMaxDynamicSharedMemorySize,
                             CNT_WORDS * 4);
        smem_set = 1;
    }

    int B = in_sizes[0] / (512 * 512);
    ca_hist_mlp_kernel<<<B, THREADS, CNT_WORDS * 4>>>(grad, W1, b1, W2, b2, out);
}